// round 14
// baseline (speedup 1.0000x reference)
#include <cuda_runtime.h>
#include <cuda_fp16.h>
#include <mma.h>
#include <cstdint>

using namespace nvcuda;

#define BB    4
#define CCH   256
#define HH    128
#define WWI   416
#define DDI   81
#define PLANE (HH*WWI)
#define MAXD  40

#define MT    64             // M tile
#define KC    32             // channels per chunk (double-buffered)
#define NCH   8              // 256/32
#define NTH   256

#define A_LD  72             // [k][m] halves
#define B_LD  152            // [k][n] halves
#define A_BYTES (KC * A_LD * 2)          // 4608
#define B_BYTES (KC * B_LD * 2)          // 9728
#define BUF_BYTES (A_BYTES + B_BYTES)    // 14336
#define SMEM_BYTES (2 * BUF_BYTES)       // 28672

#define D_LD  148            // D staging stride (149-word row step, odd -> conflict-free)

#define CSTEP ((size_t)KC * PLANE)       // gmem float advance per chunk

__global__ __launch_bounds__(NTH, 3)
void corr_pipe2(const float* __restrict__ left,
                const float* __restrict__ right,
                float* __restrict__ out) {
    extern __shared__ __align__(16) char smem[];

    const int tid  = threadIdx.x;
    const int wid  = tid >> 5;
    const int tile = blockIdx.x;                  // 0..6
    const int m0   = (tile == 6) ? 352 : tile * MT;
    const int h    = blockIdx.y, b = blockIdx.z;
    const float* lbase = left  + ((size_t)b * CCH * HH + h) * WWI;
    const float* rbase = right + ((size_t)b * CCH * HH + h) * WWI;

    // warp mapping: wmid = 16-row m stripe; wnid picks 3 of its 6 band n-tiles
    const int wmid  = wid & 3;
    const int wnid  = wid >> 2;
    const int nbase = wmid * 16 + wnid * 48;

    // ================= loop-invariant fill coordinates =================
    // A: 2 slots (512 float4 = 32k x 16)
    const float* gA[2];
    uint32_t     sA[2];                            // half-offset in A region
    #pragma unroll
    for (int i = 0; i < 2; i++) {
        const int idx = tid + i * NTH;
        const int k   = idx >> 4;
        const int mi  = (idx & 15) * 4;
        gA[i] = lbase + (size_t)k * PLANE + m0 + mi;
        sA[i] = (uint32_t)(k * A_LD + mi);
    }
    // B: 5 slots (1152 float4 = 32k x 36), slot 4 partially inactive
    const float* gB[5];
    uint32_t     sB[5];
    bool         vB[5];                            // slot active AND in-band
    #pragma unroll
    for (int i = 0; i < 5; i++) {
        const int idx = tid + i * NTH;
        const bool act = (idx < 1152);
        const int k  = act ? idx / 36 : 0;
        const int n4 = act ? (idx - k * 36) * 4 : 0;
        const int wb = m0 - MAXD + n4;
        const bool inb = act && (wb >= 0) && (wb + 3 < WWI);
        gB[i] = rbase + (size_t)k * PLANE + (inb ? wb : 0);
        sB[i] = (uint32_t)(k * B_LD + n4);
        vB[i] = inb;
        if (act && !inb) {                         // zero once; stays zero all chunks
            __half* Bs0 = (__half*)(smem + A_BYTES);
            __half* Bs1 = (__half*)(smem + BUF_BYTES + A_BYTES);
            *(uint2*)(Bs0 + sB[i]) = make_uint2(0u, 0u);
            *(uint2*)(Bs1 + sB[i]) = make_uint2(0u, 0u);
        }
    }

    float4 rA[2], rB[5];

    auto load_chunk = [&]() {
        #pragma unroll
        for (int i = 0; i < 2; i++) { rA[i] = *(const float4*)gA[i]; gA[i] += CSTEP; }
        #pragma unroll
        for (int i = 0; i < 5; i++) {
            if (vB[i]) { rB[i] = *(const float4*)gB[i]; gB[i] += CSTEP; }
        }
    };
    auto store_chunk = [&](int buf) {
        __half* As = (__half*)(smem + buf * BUF_BYTES);
        __half* Bs = (__half*)(smem + buf * BUF_BYTES + A_BYTES);
        #pragma unroll
        for (int i = 0; i < 2; i++) {
            __half2 h0 = __floats2half2_rn(rA[i].x, rA[i].y);
            __half2 h1 = __floats2half2_rn(rA[i].z, rA[i].w);
            *(uint2*)(As + sA[i]) = make_uint2(*(uint32_t*)&h0, *(uint32_t*)&h1);
        }
        #pragma unroll
        for (int i = 0; i < 5; i++) {
            if (vB[i]) {
                __half2 h0 = __floats2half2_rn(rB[i].x, rB[i].y);
                __half2 h1 = __floats2half2_rn(rB[i].z, rB[i].w);
                *(uint2*)(Bs + sB[i]) = make_uint2(*(uint32_t*)&h0, *(uint32_t*)&h1);
            }
        }
    };

    wmma::fragment<wmma::accumulator, 16, 16, 16, float> acc[3];
    #pragma unroll
    for (int j = 0; j < 3; j++) wmma::fill_fragment(acc[j], 0.0f);

    // prologue: chunk 0 into buffer 0
    load_chunk();
    store_chunk(0);
    __syncthreads();

    for (int c = 0; c < NCH; c++) {
        const int buf = c & 1;

        if (c + 1 < NCH) load_chunk();             // LDGs for c+1 before MMA on c

        const __half* As = (const __half*)(smem + buf * BUF_BYTES);
        const __half* Bs = (const __half*)(smem + buf * BUF_BYTES + A_BYTES);
        #pragma unroll
        for (int kt = 0; kt < KC / 16; kt++) {
            wmma::fragment<wmma::matrix_a, 16, 16, 16, __half, wmma::col_major> af;
            wmma::load_matrix_sync(af, As + kt * 16 * A_LD + wmid * 16, A_LD);
            #pragma unroll
            for (int j = 0; j < 3; j++) {
                wmma::fragment<wmma::matrix_b, 16, 16, 16, __half, wmma::row_major> bf;
                wmma::load_matrix_sync(bf, Bs + kt * 16 * B_LD + nbase + j * 16, B_LD);
                wmma::mma_sync(acc[j], af, bf, acc[j]);
            }
        }

        if (c + 1 < NCH) store_chunk(buf ^ 1);     // cvt+STS after MMA (LDGs landed)
        __syncthreads();
    }

    // ---- scale by 1/256 (exact power of two) ----
    #pragma unroll
    for (int j = 0; j < 3; j++)
        #pragma unroll
        for (int e = 0; e < acc[j].num_elements; e++) acc[j].x[e] *= (1.0f / 256.0f);

    // ---- epilogue in two m-half passes; Ds = [32][148] f32 = 18944 B fits ----
    float* Ds = (float*)smem;
    const int ms = (tile == 6) ? 32 : 0;          // mask overlap with tile 5
    #pragma unroll
    for (int half = 0; half < 2; half++) {
        if ((wmid >> 1) == half) {
            const int rrow = (wmid & 1) * 16;
            #pragma unroll
            for (int j = 0; j < 3; j++)
                wmma::store_matrix_sync(Ds + rrow * D_LD + nbase + j * 16,
                                        acc[j], D_LD, wmma::mem_row_major);
        }
        __syncthreads();

        const int ml = tid & 31;
        const int m  = half * 32 + ml;
        if (m >= ms) {
            for (int d = tid >> 5; d < DDI; d += 8) {
                out[(((size_t)b * DDI + d) * HH + h) * WWI + m0 + m] = Ds[ml * D_LD + m + d];
            }
        }
        __syncthreads();
    }
}

extern "C" void kernel_launch(void* const* d_in, const int* in_sizes, int n_in,
                              void* d_out, int out_size) {
    const float* left  = (const float*)d_in[0];
    const float* right = (const float*)d_in[1];
    float* out = (float*)d_out;
    (void)in_sizes; (void)n_in; (void)out_size;

    cudaFuncSetAttribute(corr_pipe2, cudaFuncAttributeMaxDynamicSharedMemorySize, SMEM_BYTES);
    dim3 grid(7, HH, BB);    // (m-tiles, h, b) = 3584 CTAs
    corr_pipe2<<<grid, NTH, SMEM_BYTES>>>(left, right, out);
}